// round 16
// baseline (speedup 1.0000x reference)
#include <cuda_runtime.h>
#include <cuda_fp16.h>
#include <cstdint>
#include <math.h>

#define L_DIM 1024
#define B_DIM 32
#define D_DIM 1024
#define M_DIM (L_DIM * B_DIM)   // 32768
#define K_DIM D_DIM             // 1024
#define N_DIM (3 * D_DIM)       // 3072
#define S_DIM (B_DIM * D_DIM)   // 32768 chains

// ---------------- scratch (device globals; no runtime allocation) ----------
__device__ __align__(16) __half g_xh[(size_t)M_DIM * K_DIM];          // 64 MB
__device__ __align__(16) __half g_wt[(size_t)N_DIM * K_DIM];          // 6 MB, tile-grouped
// pack: uint4 cell per (l/2, chain): {u0,g1 | g2,x}(l even), {u0,g1 | g2,x}(l odd)
__device__ __align__(16) __half g_packh[(size_t)M_DIM * D_DIM * 4];   // 256 MB
__device__ unsigned g_cnt[256];                                       // per-mtile done count

// ---------------- prep: x -> fp16 -------------------------------------------
__global__ void convert_x_kernel(const float4* __restrict__ x) {
    size_t i = (size_t)blockIdx.x * blockDim.x + threadIdx.x;   // M*K/4 threads
    float4 v = x[i];
    __half2 h0 = __floats2half2_rn(v.x, v.y);
    __half2 h1 = __floats2half2_rn(v.z, v.w);
    uint2 u;
    u.x = *reinterpret_cast<unsigned*>(&h0);
    u.y = *reinterpret_cast<unsigned*>(&h1);
    reinterpret_cast<uint2*>(g_xh)[i] = u;
}

__global__ void zero_cnt_kernel() { g_cnt[threadIdx.x] = 0; }

// ---------------- prep: W (K x N fp32) -> tile-grouped W^T (fp16) -----------
// original col n: d=n/3, g=n%3.  dest row = (d/32)*96 + g*32 + (d%32)
__global__ void transpose_w_kernel(const float* __restrict__ W) {
    __shared__ float tile[32][33];
    int n0 = blockIdx.x * 32, k0 = blockIdx.y * 32;
    int tx = threadIdx.x, ty = threadIdx.y;          // block (32,8)
    #pragma unroll
    for (int j = 0; j < 32; j += 8)
        tile[ty + j][tx] = W[(size_t)(k0 + ty + j) * N_DIM + n0 + tx];
    __syncthreads();
    #pragma unroll
    for (int j = 0; j < 32; j += 8) {
        int nn = n0 + ty + j;
        int d = nn / 3, g = nn % 3;
        int nperm = (d >> 5) * 96 + g * 32 + (d & 31);
        g_wt[(size_t)nperm * K_DIM + k0 + tx] = __float2half(tile[tx][ty + j]);
    }
}

// ---------------- mma.sync GEMM: u = x @ W, fused gate+pack epilogue --------
#define BM 128
#define BN 96                         // 3 gates x 32 d
#define BK 64
#define STAGES 3
#define KT (K_DIM / BK)               // 16
#define AROW 72                       // 64 + 8 halfs pad -> 144B rows, LDSM conflict-free
#define A_HALFS (BM * AROW)           // 9216
#define B_HALFS (BN * AROW)           // 6912
#define STAGE_HALFS (A_HALFS + B_HALFS)       // 16128 halfs = 32256 B
#define DYN_SMEM (STAGES * STAGE_HALFS * 2)   // 96768 B; 2 CTAs = 193.5 KB < 228 KB

__device__ __forceinline__ void load_stage(const __half* gA, const __half* gB,
                                           int tid, unsigned sA, unsigned sB,
                                           int kt, int s) {
    unsigned aS = sA + (unsigned)(s * STAGE_HALFS) * 2;
    unsigned bS = sB + (unsigned)(s * STAGE_HALFS) * 2;
    #pragma unroll
    for (int i = 0; i < 4; i++) {                         // A: 1024 chunks of 16B
        int q = tid + i * 256, row = q >> 3, ch = q & 7;
        unsigned dst = aS + (unsigned)(row * AROW + ch * 8) * 2;
        const __half* src = gA + (size_t)row * K_DIM + kt * BK + ch * 8;
        asm volatile("cp.async.cg.shared.global [%0], [%1], 16;" :: "r"(dst), "l"(src));
    }
    #pragma unroll
    for (int i = 0; i < 3; i++) {                         // B: 768 chunks of 16B
        int q = tid + i * 256, row = q >> 3, ch = q & 7;
        unsigned dst = bS + (unsigned)(row * AROW + ch * 8) * 2;
        const __half* src = gB + (size_t)row * K_DIM + kt * BK + ch * 8;
        asm volatile("cp.async.cg.shared.global [%0], [%1], 16;" :: "r"(dst), "l"(src));
    }
}

__global__ void __launch_bounds__(256, 2) gemm_kernel(const float* __restrict__ bias) {
    extern __shared__ __half smem[];
    __shared__ float s_b1[32], s_b2[32];

    const int tid = threadIdx.x, wid = tid >> 5, lane = tid & 31;
    const int ntile = blockIdx.x, mtile = blockIdx.y;
    const int d0 = ntile * 32;

    if (tid < 32) {
        s_b1[tid] = bias[d0 + tid];
        s_b2[tid] = bias[D_DIM + d0 + tid];
    }

    const __half* gA = g_xh + (size_t)mtile * BM * K_DIM;
    const __half* gB = g_wt + (size_t)ntile * BN * K_DIM;

    const unsigned sA = (unsigned)__cvta_generic_to_shared(smem);
    const unsigned sB = sA + A_HALFS * 2;

    // warp tiling: 4 warps in M (32 rows each), 2 warps in N (48 cols each)
    const int warp_m = (wid >> 1) * 32;
    const int warp_n = (wid & 1) * 48;

    float acc[2][6][4];
    #pragma unroll
    for (int i = 0; i < 2; i++)
        #pragma unroll
        for (int j = 0; j < 6; j++)
            #pragma unroll
            for (int e = 0; e < 4; e++) acc[i][j][e] = 0.f;

    const int a_row = warp_m + (lane & 15);
    const int a_kof = (lane >> 4) * 8;
    const int b_row = warp_n + (lane & 7) + ((lane >> 4) << 3);
    const int b_kof = ((lane >> 3) & 1) * 8;

    load_stage(gA, gB, tid, sA, sB, 0, 0); asm volatile("cp.async.commit_group;");
    load_stage(gA, gB, tid, sA, sB, 1, 1); asm volatile("cp.async.commit_group;");

    for (int kt = 0; kt < KT; kt++) {
        asm volatile("cp.async.wait_group 1;");
        __syncthreads();
        if (kt + 2 < KT) load_stage(gA, gB, tid, sA, sB, kt + 2, (kt + 2) % 3);
        asm volatile("cp.async.commit_group;");

        const int st = kt % 3;
        const unsigned aS = sA + (unsigned)(st * STAGE_HALFS) * 2;
        const unsigned bS = sB + (unsigned)(st * STAGE_HALFS) * 2;

        #pragma unroll
        for (int kk = 0; kk < 4; kk++) {
            const int k16 = kk * 16;
            unsigned ar[2][4];
            #pragma unroll
            for (int i = 0; i < 2; i++) {
                unsigned addr = aS + (unsigned)(((a_row + i * 16) * AROW) + k16 + a_kof) * 2;
                asm volatile("ldmatrix.sync.aligned.m8n8.x4.shared.b16 {%0,%1,%2,%3}, [%4];\n"
                    : "=r"(ar[i][0]), "=r"(ar[i][1]), "=r"(ar[i][2]), "=r"(ar[i][3]) : "r"(addr));
            }
            unsigned br[3][4];
            #pragma unroll
            for (int jt = 0; jt < 3; jt++) {
                unsigned addr = bS + (unsigned)(((b_row + jt * 16) * AROW) + k16 + b_kof) * 2;
                asm volatile("ldmatrix.sync.aligned.m8n8.x4.shared.b16 {%0,%1,%2,%3}, [%4];\n"
                    : "=r"(br[jt][0]), "=r"(br[jt][1]), "=r"(br[jt][2]), "=r"(br[jt][3]) : "r"(addr));
            }
            #pragma unroll
            for (int i = 0; i < 2; i++)
                #pragma unroll
                for (int jt = 0; jt < 3; jt++)
                    #pragma unroll
                    for (int f = 0; f < 2; f++) {
                        const int j = jt * 2 + f;
                        asm volatile(
                            "mma.sync.aligned.m16n8k16.row.col.f32.f16.f16.f32 "
                            "{%0,%1,%2,%3}, {%4,%5,%6,%7}, {%8,%9}, {%0,%1,%2,%3};\n"
                            : "+f"(acc[i][j][0]), "+f"(acc[i][j][1]),
                              "+f"(acc[i][j][2]), "+f"(acc[i][j][3])
                            : "r"(ar[i][0]), "r"(ar[i][1]), "r"(ar[i][2]), "r"(ar[i][3]),
                              "r"(br[jt][f * 2]), "r"(br[jt][f * 2 + 1]));
                    }
        }
    }
    asm volatile("cp.async.wait_group 0;");
    __syncthreads();                                  // stages dead; reuse smem as tbuf

    // ---- epilogue: gates -> smem [m][g*33+dd] -> paired-L 16B pack ---------
    float* tbuf = (float*)smem;                       // 128 * 99 * 4 = 50688 B
    #pragma unroll
    for (int i = 0; i < 2; i++)
        #pragma unroll
        for (int j = 0; j < 6; j++)
            #pragma unroll
            for (int e = 0; e < 4; e++) {
                int m = warp_m + i * 16 + (lane >> 2) + ((e >= 2) ? 8 : 0);
                int c = warp_n + j * 8 + 2 * (lane & 3) + (e & 1);
                int g = c >> 5, dd = c & 31;
                float v = acc[i][j][e];
                if (g == 1) v = 1.0f / (1.0f + __expf(-(v + s_b1[dd])));
                else if (g == 2) v = 1.0f / (1.0f + __expf(-(v + s_b2[dd])));
                tbuf[m * 99 + g * 33 + dd] = v;
            }
    __syncthreads();

    // rows r and r+32 differ by exactly one l; pair them into one 16B cell.
    const int l0 = mtile * 4;                         // first l of this tile
    uint4* pk4 = (uint4*)g_packh;
    const size_t gm0 = (size_t)mtile * BM;
    #pragma unroll
    for (int pi = 0; pi < 8; pi++) {
        int p = wid * 8 + pi;                         // 0..63 pair id
        int rowE = (p & 31) + ((p >= 32) ? 64 : 0);   // even-l row
        int rowO = rowE + 32;                         // odd-l row
        int b = p & 31;
        int lpair = (l0 >> 1) + ((p >= 32) ? 1 : 0);
        size_t sidx = (size_t)b * D_DIM + d0 + lane;  // chain id

        __half xhE = g_xh[(gm0 + rowE) * K_DIM + d0 + lane];
        __half xhO = g_xh[(gm0 + rowO) * K_DIM + d0 + lane];

        __half2 e01 = __floats2half2_rn(tbuf[rowE * 99 + 0 * 33 + lane],
                                        tbuf[rowE * 99 + 1 * 33 + lane]);
        __half2 e23; e23.x = __float2half_rn(tbuf[rowE * 99 + 2 * 33 + lane]); e23.y = xhE;
        __half2 o01 = __floats2half2_rn(tbuf[rowO * 99 + 0 * 33 + lane],
                                        tbuf[rowO * 99 + 1 * 33 + lane]);
        __half2 o23; o23.x = __float2half_rn(tbuf[rowO * 99 + 2 * 33 + lane]); o23.y = xhO;

        uint4 pv;
        pv.x = *reinterpret_cast<unsigned*>(&e01);
        pv.y = *reinterpret_cast<unsigned*>(&e23);
        pv.z = *reinterpret_cast<unsigned*>(&o01);
        pv.w = *reinterpret_cast<unsigned*>(&o23);
        pk4[(size_t)lpair * S_DIM + sidx] = pv;       // coalesced 16B stores
    }

    // ---- release: publish this mtile's pack rows (count hits 32 = ready) ---
    __threadfence();
    __syncthreads();
    if (tid == 0) atomicAdd(&g_cnt[mtile], 1);
}

// ---------------- sequential scan over L + output (overlapped) --------------
// Balanced persistent mapping: grid=148 (1 CTA/SM), 8 warps/CTA.
// Runs CONCURRENTLY with gemm_kernel (stream fork); consumes mtiles as their
// g_cnt reaches 32 (all 32 ntile CTAs done), acquire-polled with backoff.
#define PF4 16    // 16 x uint4 = 256B in flight per thread, 32 l-steps per iter
#define SCAN_GRID 148
#define NCHUNK (S_DIM / 32)   // 1024 chain-chunks of one warp each

__global__ void __launch_bounds__(256, 1) scan_kernel(const float* __restrict__ c0,
                                                      float* __restrict__ out) {
    const int wid = threadIdx.x >> 5, lane = threadIdx.x & 31;
    const int chunk = wid * SCAN_GRID + blockIdx.x;
    if (chunk >= NCHUNK) return;
    const int tid = chunk * 32 + lane;                       // chain id
    float c = c0[tid];
    const uint4* pk4 = (const uint4*)g_packh;

    for (int lp = 0; lp < L_DIM / 2; lp += PF4) {
        // wait for the 8 mtiles covering lpairs [lp, lp+PF4)
        if (lane == 0) {
            #pragma unroll
            for (int m = 0; m < 8; m++) {
                unsigned v;
                do {
                    asm volatile("ld.acquire.gpu.global.u32 %0, [%1];"
                                 : "=r"(v) : "l"(g_cnt + (lp >> 1) + m) : "memory");
                    if (v < 32) __nanosleep(64);
                } while (v < 32);
            }
        }
        __syncwarp();

        uint4 v[PF4];
        #pragma unroll
        for (int p = 0; p < PF4; p++)
            v[p] = __ldg(pk4 + (size_t)(lp + p) * S_DIM + tid);
        #pragma unroll
        for (int p = 0; p < PF4; p++) {
            __half2 e01 = *reinterpret_cast<__half2*>(&v[p].x);
            __half2 e23 = *reinterpret_cast<__half2*>(&v[p].y);
            __half2 o01 = *reinterpret_cast<__half2*>(&v[p].z);
            __half2 o23 = *reinterpret_cast<__half2*>(&v[p].w);
            int l = 2 * (lp + p);

            float u0 = __low2float(e01), g1 = __high2float(e01);
            float g2 = __low2float(e23), xv = __high2float(e23);
            c = (c - u0) * g1 + u0;
            float e = __expf(2.0f * c);
            float t = 1.0f - __fdividef(2.0f, e + 1.0f);
            out[(size_t)l * S_DIM + tid] = (t - xv) * g2 + xv;

            u0 = __low2float(o01); g1 = __high2float(o01);
            g2 = __low2float(o23); xv = __high2float(o23);
            c = (c - u0) * g1 + u0;
            e = __expf(2.0f * c);
            t = 1.0f - __fdividef(2.0f, e + 1.0f);
            out[(size_t)(l + 1) * S_DIM + tid] = (t - xv) * g2 + xv;
        }
    }
}

// ---------------- launch: fork scan concurrent with GEMM --------------------
extern "C" void kernel_launch(void* const* d_in, const int* in_sizes, int n_in,
                              void* d_out, int out_size) {
    const float* x    = (const float*)d_in[0];
    const float* W    = (const float*)d_in[1];
    const float* bias = (const float*)d_in[2];
    const float* c0   = (const float*)d_in[3];
    float* out = (float*)d_out;

    static cudaStream_t s2 = nullptr;
    static cudaEvent_t evF = nullptr, evJ = nullptr;
    if (s2 == nullptr) {
        cudaStreamCreateWithFlags(&s2, cudaStreamNonBlocking);
        cudaEventCreateWithFlags(&evF, cudaEventDisableTiming);
        cudaEventCreateWithFlags(&evJ, cudaEventDisableTiming);
    }

    convert_x_kernel<<<(M_DIM * K_DIM / 4) / 256, 256>>>((const float4*)x);
    transpose_w_kernel<<<dim3(N_DIM / 32, K_DIM / 32), dim3(32, 8)>>>(W);
    zero_cnt_kernel<<<1, 256>>>();

    cudaEventRecord(evF, 0);               // fork point (after prep + zeroing)
    cudaStreamWaitEvent(s2, evF, 0);

    cudaFuncSetAttribute(gemm_kernel, cudaFuncAttributeMaxDynamicSharedMemorySize, DYN_SMEM);
    gemm_kernel<<<dim3(D_DIM / 32, M_DIM / BM), 256, DYN_SMEM>>>(bias);   // main stream
    scan_kernel<<<SCAN_GRID, 256, 0, s2>>>(c0, out);                      // concurrent

    cudaEventRecord(evJ, s2);              // join: d_out ready only after scan
    cudaStreamWaitEvent(0, evJ, 0);
}

// round 17
// speedup vs baseline: 1.0915x; 1.0915x over previous
#include <cuda_runtime.h>
#include <cuda_fp16.h>
#include <cstdint>
#include <math.h>

#define L_DIM 1024
#define B_DIM 32
#define D_DIM 1024
#define M_DIM (L_DIM * B_DIM)   // 32768
#define K_DIM D_DIM             // 1024
#define N_DIM (3 * D_DIM)       // 3072
#define S_DIM (B_DIM * D_DIM)   // 32768 chains

// ---------------- scratch (device globals; no runtime allocation) ----------
__device__ __align__(16) __half g_xh[(size_t)M_DIM * K_DIM];          // 64 MB
__device__ __align__(16) __half g_wt[(size_t)N_DIM * K_DIM];          // 6 MB, tile-grouped
// pack: uint4 cell per (l/2, chain): {u0,g1 | g2,x}(l even), {u0,g1 | g2,x}(l odd)
__device__ __align__(16) __half g_packh[(size_t)M_DIM * D_DIM * 4];   // 256 MB

// ---------------- prep: x -> fp16 -------------------------------------------
__global__ void convert_x_kernel(const float4* __restrict__ x) {
    size_t i = (size_t)blockIdx.x * blockDim.x + threadIdx.x;   // M*K/4 threads
    float4 v = x[i];
    __half2 h0 = __floats2half2_rn(v.x, v.y);
    __half2 h1 = __floats2half2_rn(v.z, v.w);
    uint2 u;
    u.x = *reinterpret_cast<unsigned*>(&h0);
    u.y = *reinterpret_cast<unsigned*>(&h1);
    reinterpret_cast<uint2*>(g_xh)[i] = u;
}

// ---------------- prep: W (K x N fp32) -> tile-grouped W^T (fp16) -----------
// original col n: d=n/3, g=n%3.  dest row = (d/32)*96 + g*32 + (d%32)
__global__ void transpose_w_kernel(const float* __restrict__ W) {
    __shared__ float tile[32][33];
    int n0 = blockIdx.x * 32, k0 = blockIdx.y * 32;
    int tx = threadIdx.x, ty = threadIdx.y;          // block (32,8)
    #pragma unroll
    for (int j = 0; j < 32; j += 8)
        tile[ty + j][tx] = W[(size_t)(k0 + ty + j) * N_DIM + n0 + tx];
    __syncthreads();
    #pragma unroll
    for (int j = 0; j < 32; j += 8) {
        int nn = n0 + ty + j;
        int d = nn / 3, g = nn % 3;
        int nperm = (d >> 5) * 96 + g * 32 + (d & 31);
        g_wt[(size_t)nperm * K_DIM + k0 + tx] = __float2half(tile[tx][ty + j]);
    }
}

// ---------------- mma.sync GEMM: u = x @ W, fused gate+pack epilogue --------
// 384 threads (12 warps: 4 in M x 3 in N, warp tile 32x32) -> 6 warps/SMSP at
// 2 CTAs/SM, acc 32 regs/thread. Same tile/work as before; pure latency hiding.
#define BM 128
#define BN 96                         // 3 gates x 32 d
#define BK 64
#define STAGES 3
#define KT (K_DIM / BK)               // 16
#define NTHR 384
#define AROW 72                       // 64 + 8 halfs pad -> 144B rows, LDSM conflict-free
#define A_HALFS (BM * AROW)           // 9216
#define B_HALFS (BN * AROW)           // 6912
#define STAGE_HALFS (A_HALFS + B_HALFS)       // 16128 halfs = 32256 B
#define DYN_SMEM (STAGES * STAGE_HALFS * 2)   // 96768 B; 2 CTAs = 193.5 KB < 228 KB

__device__ __forceinline__ void load_stage(const __half* gA, const __half* gB,
                                           int tid, unsigned sA, unsigned sB,
                                           int kt, int s) {
    unsigned aS = sA + (unsigned)(s * STAGE_HALFS) * 2;
    unsigned bS = sB + (unsigned)(s * STAGE_HALFS) * 2;
    #pragma unroll 3
    for (int q = tid; q < 1024; q += NTHR) {              // A: 1024 chunks of 16B
        int row = q >> 3, ch = q & 7;
        unsigned dst = aS + (unsigned)(row * AROW + ch * 8) * 2;
        const __half* src = gA + (size_t)row * K_DIM + kt * BK + ch * 8;
        asm volatile("cp.async.cg.shared.global [%0], [%1], 16;" :: "r"(dst), "l"(src));
    }
    #pragma unroll
    for (int i = 0; i < 2; i++) {                         // B: 768 chunks of 16B
        int q = tid + i * NTHR;
        int row = q >> 3, ch = q & 7;
        unsigned dst = bS + (unsigned)(row * AROW + ch * 8) * 2;
        const __half* src = gB + (size_t)row * K_DIM + kt * BK + ch * 8;
        asm volatile("cp.async.cg.shared.global [%0], [%1], 16;" :: "r"(dst), "l"(src));
    }
}

__global__ void __launch_bounds__(NTHR, 2) gemm_kernel(const float* __restrict__ bias) {
    extern __shared__ __half smem[];
    __shared__ float s_b1[32], s_b2[32];

    const int tid = threadIdx.x, wid = tid >> 5, lane = tid & 31;
    const int ntile = blockIdx.x, mtile = blockIdx.y;
    const int d0 = ntile * 32;

    if (tid < 32) {
        s_b1[tid] = bias[d0 + tid];
        s_b2[tid] = bias[D_DIM + d0 + tid];
    }

    const __half* gA = g_xh + (size_t)mtile * BM * K_DIM;
    const __half* gB = g_wt + (size_t)ntile * BN * K_DIM;

    const unsigned sA = (unsigned)__cvta_generic_to_shared(smem);
    const unsigned sB = sA + A_HALFS * 2;

    // 12 warps: 4 in M (32 rows), 3 in N (32 cols = one gate each)
    const int warp_m = (wid / 3) * 32;
    const int warp_n = (wid % 3) * 32;

    float acc[2][4][4];
    #pragma unroll
    for (int i = 0; i < 2; i++)
        #pragma unroll
        for (int j = 0; j < 4; j++)
            #pragma unroll
            for (int e = 0; e < 4; e++) acc[i][j][e] = 0.f;

    const int a_row = warp_m + (lane & 15);
    const int a_kof = (lane >> 4) * 8;
    const int b_row = warp_n + (lane & 7) + ((lane >> 4) << 3);
    const int b_kof = ((lane >> 3) & 1) * 8;

    load_stage(gA, gB, tid, sA, sB, 0, 0); asm volatile("cp.async.commit_group;");
    load_stage(gA, gB, tid, sA, sB, 1, 1); asm volatile("cp.async.commit_group;");

    for (int kt = 0; kt < KT; kt++) {
        asm volatile("cp.async.wait_group 1;");
        __syncthreads();
        if (kt + 2 < KT) load_stage(gA, gB, tid, sA, sB, kt + 2, (kt + 2) % 3);
        asm volatile("cp.async.commit_group;");

        const int st = kt % 3;
        const unsigned aS = sA + (unsigned)(st * STAGE_HALFS) * 2;
        const unsigned bS = sB + (unsigned)(st * STAGE_HALFS) * 2;

        #pragma unroll
        for (int kk = 0; kk < 4; kk++) {
            const int k16 = kk * 16;
            unsigned ar[2][4];
            #pragma unroll
            for (int i = 0; i < 2; i++) {
                unsigned addr = aS + (unsigned)(((a_row + i * 16) * AROW) + k16 + a_kof) * 2;
                asm volatile("ldmatrix.sync.aligned.m8n8.x4.shared.b16 {%0,%1,%2,%3}, [%4];\n"
                    : "=r"(ar[i][0]), "=r"(ar[i][1]), "=r"(ar[i][2]), "=r"(ar[i][3]) : "r"(addr));
            }
            unsigned br[2][4];
            #pragma unroll
            for (int jt = 0; jt < 2; jt++) {
                unsigned addr = bS + (unsigned)(((b_row + jt * 16) * AROW) + k16 + b_kof) * 2;
                asm volatile("ldmatrix.sync.aligned.m8n8.x4.shared.b16 {%0,%1,%2,%3}, [%4];\n"
                    : "=r"(br[jt][0]), "=r"(br[jt][1]), "=r"(br[jt][2]), "=r"(br[jt][3]) : "r"(addr));
            }
            #pragma unroll
            for (int i = 0; i < 2; i++)
                #pragma unroll
                for (int jt = 0; jt < 2; jt++)
                    #pragma unroll
                    for (int f = 0; f < 2; f++) {
                        const int j = jt * 2 + f;
                        asm volatile(
                            "mma.sync.aligned.m16n8k16.row.col.f32.f16.f16.f32 "
                            "{%0,%1,%2,%3}, {%4,%5,%6,%7}, {%8,%9}, {%0,%1,%2,%3};\n"
                            : "+f"(acc[i][j][0]), "+f"(acc[i][j][1]),
                              "+f"(acc[i][j][2]), "+f"(acc[i][j][3])
                            : "r"(ar[i][0]), "r"(ar[i][1]), "r"(ar[i][2]), "r"(ar[i][3]),
                              "r"(br[jt][f * 2]), "r"(br[jt][f * 2 + 1]));
                    }
        }
    }
    asm volatile("cp.async.wait_group 0;");
    __syncthreads();                                  // stages dead; reuse smem as tbuf

    // ---- epilogue: gates -> smem [m][g*33+dd] -> paired-L 16B pack ---------
    float* tbuf = (float*)smem;                       // 128 * 99 * 4 = 50688 B
    #pragma unroll
    for (int i = 0; i < 2; i++)
        #pragma unroll
        for (int j = 0; j < 4; j++)
            #pragma unroll
            for (int e = 0; e < 4; e++) {
                int m = warp_m + i * 16 + (lane >> 2) + ((e >= 2) ? 8 : 0);
                int c = warp_n + j * 8 + 2 * (lane & 3) + (e & 1);
                int g = c >> 5, dd = c & 31;
                float v = acc[i][j][e];
                if (g == 1) v = 1.0f / (1.0f + __expf(-(v + s_b1[dd])));
                else if (g == 2) v = 1.0f / (1.0f + __expf(-(v + s_b2[dd])));
                tbuf[m * 99 + g * 33 + dd] = v;
            }
    __syncthreads();

    // rows r and r+32 differ by exactly one l; pair them into one 16B cell.
    const int l0 = mtile * 4;                         // first l of this tile
    uint4* pk4 = (uint4*)g_packh;
    const size_t gm0 = (size_t)mtile * BM;
    for (int p = wid; p < 64; p += 12) {              // 64 pair ids over 12 warps
        int rowE = (p & 31) + ((p >= 32) ? 64 : 0);   // even-l row
        int rowO = rowE + 32;                         // odd-l row
        int b = p & 31;
        int lpair = (l0 >> 1) + ((p >= 32) ? 1 : 0);
        size_t sidx = (size_t)b * D_DIM + d0 + lane;  // chain id

        __half xhE = g_xh[(gm0 + rowE) * K_DIM + d0 + lane];
        __half xhO = g_xh[(gm0 + rowO) * K_DIM + d0 + lane];

        __half2 e01 = __floats2half2_rn(tbuf[rowE * 99 + 0 * 33 + lane],
                                        tbuf[rowE * 99 + 1 * 33 + lane]);
        __half2 e23; e23.x = __float2half_rn(tbuf[rowE * 99 + 2 * 33 + lane]); e23.y = xhE;
        __half2 o01 = __floats2half2_rn(tbuf[rowO * 99 + 0 * 33 + lane],
                                        tbuf[rowO * 99 + 1 * 33 + lane]);
        __half2 o23; o23.x = __float2half_rn(tbuf[rowO * 99 + 2 * 33 + lane]); o23.y = xhO;

        uint4 pv;
        pv.x = *reinterpret_cast<unsigned*>(&e01);
        pv.y = *reinterpret_cast<unsigned*>(&e23);
        pv.z = *reinterpret_cast<unsigned*>(&o01);
        pv.w = *reinterpret_cast<unsigned*>(&o23);
        pk4[(size_t)lpair * S_DIM + sidx] = pv;       // coalesced 16B stores
    }
}

// ---------------- sequential scan over L + output ---------------------------
// Balanced persistent mapping: grid=148 (1 CTA/SM), 8 warps/CTA (proven R14).
#define PF4 16    // 16 x uint4 = 256B in flight per thread, 32 l-steps per iter
#define SCAN_GRID 148
#define NCHUNK (S_DIM / 32)   // 1024 chain-chunks of one warp each

__global__ void __launch_bounds__(256, 1) scan_kernel(const float* __restrict__ c0,
                                                      float* __restrict__ out) {
    const int wid = threadIdx.x >> 5, lane = threadIdx.x & 31;
    const int chunk = wid * SCAN_GRID + blockIdx.x;
    if (chunk >= NCHUNK) return;
    const int tid = chunk * 32 + lane;                       // chain id
    float c = c0[tid];
    const uint4* pk4 = (const uint4*)g_packh;

    for (int lp = 0; lp < L_DIM / 2; lp += PF4) {
        uint4 v[PF4];
        #pragma unroll
        for (int p = 0; p < PF4; p++)
            v[p] = __ldg(pk4 + (size_t)(lp + p) * S_DIM + tid);
        #pragma unroll
        for (int p = 0; p < PF4; p++) {
            __half2 e01 = *reinterpret_cast<__half2*>(&v[p].x);
            __half2 e23 = *reinterpret_cast<__half2*>(&v[p].y);
            __half2 o01 = *reinterpret_cast<__half2*>(&v[p].z);
            __half2 o23 = *reinterpret_cast<__half2*>(&v[p].w);
            int l = 2 * (lp + p);

            float u0 = __low2float(e01), g1 = __high2float(e01);
            float g2 = __low2float(e23), xv = __high2float(e23);
            c = (c - u0) * g1 + u0;
            float e = __expf(2.0f * c);
            float t = 1.0f - __fdividef(2.0f, e + 1.0f);
            out[(size_t)l * S_DIM + tid] = (t - xv) * g2 + xv;

            u0 = __low2float(o01); g1 = __high2float(o01);
            g2 = __low2float(o23); xv = __high2float(o23);
            c = (c - u0) * g1 + u0;
            e = __expf(2.0f * c);
            t = 1.0f - __fdividef(2.0f, e + 1.0f);
            out[(size_t)(l + 1) * S_DIM + tid] = (t - xv) * g2 + xv;
        }
    }
}

// ---------------- launch (sequential; overlap reverted) ---------------------
extern "C" void kernel_launch(void* const* d_in, const int* in_sizes, int n_in,
                              void* d_out, int out_size) {
    const float* x    = (const float*)d_in[0];
    const float* W    = (const float*)d_in[1];
    const float* bias = (const float*)d_in[2];
    const float* c0   = (const float*)d_in[3];
    float* out = (float*)d_out;

    convert_x_kernel<<<(M_DIM * K_DIM / 4) / 256, 256>>>((const float4*)x);
    transpose_w_kernel<<<dim3(N_DIM / 32, K_DIM / 32), dim3(32, 8)>>>(W);

    cudaFuncSetAttribute(gemm_kernel, cudaFuncAttributeMaxDynamicSharedMemorySize, DYN_SMEM);
    gemm_kernel<<<dim3(D_DIM / 32, M_DIM / BM), NTHR, DYN_SMEM>>>(bias);

    scan_kernel<<<SCAN_GRID, 256>>>(c0, out);
}